// round 3
// baseline (speedup 1.0000x reference)
#include <cuda_runtime.h>

// CausalConv1d: y[b,l,d] = bias[d] + sum_{k=0..3} x[b, l-3+k, d] * w[d,0,k]
// x: (B=8, L=4096, D=1024) fp32, D innermost. w: (D,1,4). b: (D,). Out: (B,L,D).
//
// HBM-bound. Single exact wave: 592 blocks (148 SM x 4 resident), each block
// owns a contiguous range of ~55 flattened L-rows; 256 threads = float4 lanes
// over D; sliding 3-register window over L. x read once (+3-row halo per
// range = 5.5%), y written once with streaming stores.

#define CC_B 8
#define CC_L 4096
#define CC_D 1024
#define CC_K 4
#define CC_DV (CC_D / 4)             // 256 float4 lanes over D
#define CC_ROWS (CC_B * CC_L)        // 32768 flattened rows
#define CC_GRID 592                  // 148 SMs * 4 blocks
#define CC_LMASK (CC_L - 1)

__global__ __launch_bounds__(CC_DV, 4)
void causal_conv1d_kernel(const float4* __restrict__ x,
                          const float*  __restrict__ w,
                          const float4* __restrict__ bias,
                          float4*       __restrict__ y)
{
    const int d4 = threadIdx.x;      // 0..255
    const int d0 = d4 * 4;

    // Even split of 32768 rows over 592 blocks: base 55, first 208 get 56.
    const int base = CC_ROWS / CC_GRID;          // 55
    const int rem  = CC_ROWS % CC_GRID;          // 208
    const int i    = blockIdx.x;
    int r0 = i * base + (i < rem ? i : rem);
    const int r1 = r0 + base + (i < rem ? 1 : 0);

    // Per-lane weights: 4 channels x 4 taps. w[d*K + k].
    const float w0x = w[(d0 + 0) * CC_K + 0], w1x = w[(d0 + 0) * CC_K + 1],
                w2x = w[(d0 + 0) * CC_K + 2], w3x = w[(d0 + 0) * CC_K + 3];
    const float w0y = w[(d0 + 1) * CC_K + 0], w1y = w[(d0 + 1) * CC_K + 1],
                w2y = w[(d0 + 1) * CC_K + 2], w3y = w[(d0 + 1) * CC_K + 3];
    const float w0z = w[(d0 + 2) * CC_K + 0], w1z = w[(d0 + 2) * CC_K + 1],
                w2z = w[(d0 + 2) * CC_K + 2], w3z = w[(d0 + 2) * CC_K + 3];
    const float w0w = w[(d0 + 3) * CC_K + 0], w1w = w[(d0 + 3) * CC_K + 1],
                w2w = w[(d0 + 3) * CC_K + 2], w3w = w[(d0 + 3) * CC_K + 3];

    const float4 bv = bias[d4];
    const float4 z4 = make_float4(0.f, 0.f, 0.f, 0.f);

    // Process [r0, r1), split at batch boundaries (a range crosses at most one).
    while (r0 < r1) {
        const int b  = r0 >> 12;                 // r0 / L
        const int l0 = r0 & CC_LMASK;
        int seg_end = (b + 1) << 12;             // first row of next batch
        if (seg_end > r1) seg_end = r1;

        // Window init at (b, l0): x[l0-3..l0-1], zeros before l=0.
        float4 xm3 = (l0 >= 3) ? x[(size_t)(r0 - 3) * CC_DV + d4] : z4;
        float4 xm2 = (l0 >= 2) ? x[(size_t)(r0 - 2) * CC_DV + d4] : z4;
        float4 xm1 = (l0 >= 1) ? x[(size_t)(r0 - 1) * CC_DV + d4] : z4;

        #pragma unroll 4
        for (int r = r0; r < seg_end; r++) {
            const size_t off = (size_t)r * CC_DV + d4;
            const float4 xc = x[off];
            float4 o;
            o.x = fmaf(w0x, xm3.x, fmaf(w1x, xm2.x, fmaf(w2x, xm1.x, fmaf(w3x, xc.x, bv.x))));
            o.y = fmaf(w0y, xm3.y, fmaf(w1y, xm2.y, fmaf(w2y, xm1.y, fmaf(w3y, xc.y, bv.y))));
            o.z = fmaf(w0z, xm3.z, fmaf(w1z, xm2.z, fmaf(w2z, xm1.z, fmaf(w3z, xc.z, bv.z))));
            o.w = fmaf(w0w, xm3.w, fmaf(w1w, xm2.w, fmaf(w2w, xm1.w, fmaf(w3w, xc.w, bv.w))));
            __stcs(&y[off], o);                  // streaming store: evict-first in L2
            xm3 = xm2;
            xm2 = xm1;
            xm1 = xc;
        }
        r0 = seg_end;
    }
}

extern "C" void kernel_launch(void* const* d_in, const int* in_sizes, int n_in,
                              void* d_out, int out_size)
{
    (void)in_sizes; (void)n_in; (void)out_size;
    const float4* x    = (const float4*)d_in[0];
    const float*  w    = (const float*)d_in[1];
    const float4* bias = (const float4*)d_in[2];
    float4*       y    = (float4*)d_out;

    causal_conv1d_kernel<<<CC_GRID, CC_DV>>>(x, w, bias, y);
}

// round 5
// speedup vs baseline: 1.1781x; 1.1781x over previous
#include <cuda_runtime.h>

// CausalConv1d: y[b,l,d] = bias[d] + sum_{k=0..3} x[b, l-3+k, d] * w[d,0,k]
// x: (B=8, L=4096, D=1024) fp32, D innermost. w: (D,1,4). b: (D,). Out: (B,L,D).
//
// HBM-bound. Schedule: 592 blocks = one exact wave (148 SM x 4 resident).
// 74 blocks per batch, each handling EXACTLY 56 rows (7x8 fully unrolled,
// fixed trip count -> compiler batches LDG.128s). Ranges overlap by <=1 row
// (identical recompute, benign). Inner loop is byte-identical to the R2
// kernel that measured best codegen.

#define CC_B 8
#define CC_L 4096
#define CC_D 1024
#define CC_K 4
#define CC_DV (CC_D / 4)         // 256 float4 lanes over D
#define CC_BPB 74                // blocks per batch
#define CC_LC 56                 // rows per block (7 x 8)
#define CC_GRID (CC_B * CC_BPB)  // 592 = 148 SMs * 4

__global__ __launch_bounds__(CC_DV, 4)
void causal_conv1d_kernel(const float4* __restrict__ x,
                          const float*  __restrict__ w,
                          const float4* __restrict__ bias,
                          float4*       __restrict__ y)
{
    const int d4 = threadIdx.x;              // 0..255
    const int d0 = d4 * 4;

    const int b = blockIdx.x / CC_BPB;       // batch
    const int j = blockIdx.x % CC_BPB;       // block within batch
    // Start row within batch: j * (L - LC) / (BPB - 1); spacing 55/56 <= LC,
    // so [0, L) is covered; overlaps recompute identical values.
    const int l0 = (j * (CC_L - CC_LC)) / (CC_BPB - 1);

    // Per-lane weights: 4 channels x 4 taps. w[d*K + k].
    const float w0x = w[(d0 + 0) * CC_K + 0], w1x = w[(d0 + 0) * CC_K + 1],
                w2x = w[(d0 + 0) * CC_K + 2], w3x = w[(d0 + 0) * CC_K + 3];
    const float w0y = w[(d0 + 1) * CC_K + 0], w1y = w[(d0 + 1) * CC_K + 1],
                w2y = w[(d0 + 1) * CC_K + 2], w3y = w[(d0 + 1) * CC_K + 3];
    const float w0z = w[(d0 + 2) * CC_K + 0], w1z = w[(d0 + 2) * CC_K + 1],
                w2z = w[(d0 + 2) * CC_K + 2], w3z = w[(d0 + 2) * CC_K + 3];
    const float w0w = w[(d0 + 3) * CC_K + 0], w1w = w[(d0 + 3) * CC_K + 1],
                w2w = w[(d0 + 3) * CC_K + 2], w3w = w[(d0 + 3) * CC_K + 3];

    const float4 bv = bias[d4];

    const size_t rowbase = (size_t)b * CC_L * CC_DV + d4;  // + l*CC_DV per row

    // Sliding window: x at l0-3, l0-2, l0-1 (zeros before l=0; only j==0 pads).
    float4 xm3, xm2, xm1;
    if (l0 == 0) {
        xm3 = make_float4(0.f, 0.f, 0.f, 0.f);
        xm2 = xm3;
        xm1 = xm3;
    } else {
        xm3 = x[rowbase + (size_t)(l0 - 3) * CC_DV];
        xm2 = x[rowbase + (size_t)(l0 - 2) * CC_DV];
        xm1 = x[rowbase + (size_t)(l0 - 1) * CC_DV];
    }

    #pragma unroll 8
    for (int i = 0; i < CC_LC; i++) {
        const size_t off = rowbase + (size_t)(l0 + i) * CC_DV;
        const float4 xc = x[off];
        float4 r;
        r.x = fmaf(w0x, xm3.x, fmaf(w1x, xm2.x, fmaf(w2x, xm1.x, fmaf(w3x, xc.x, bv.x))));
        r.y = fmaf(w0y, xm3.y, fmaf(w1y, xm2.y, fmaf(w2y, xm1.y, fmaf(w3y, xc.y, bv.y))));
        r.z = fmaf(w0z, xm3.z, fmaf(w1z, xm2.z, fmaf(w2z, xm1.z, fmaf(w3z, xc.z, bv.z))));
        r.w = fmaf(w0w, xm3.w, fmaf(w1w, xm2.w, fmaf(w2w, xm1.w, fmaf(w3w, xc.w, bv.w))));
        y[off] = r;
        xm3 = xm2;
        xm2 = xm1;
        xm1 = xc;
    }
}

extern "C" void kernel_launch(void* const* d_in, const int* in_sizes, int n_in,
                              void* d_out, int out_size)
{
    (void)in_sizes; (void)n_in; (void)out_size;
    const float4* x    = (const float4*)d_in[0];
    const float*  w    = (const float*)d_in[1];
    const float4* bias = (const float4*)d_in[2];
    float4*       y    = (float4*)d_out;

    causal_conv1d_kernel<<<CC_GRID, CC_DV>>>(x, w, bias, y);
}

// round 6
// speedup vs baseline: 1.3478x; 1.1440x over previous
#include <cuda_runtime.h>

// CausalConv1d: y[b,l,d] = bias[d] + sum_{k=0..3} x[b, l-3+k, d] * w[d,0,k]
// x: (B=8, L=4096, D=1024) fp32, D innermost. w: (D,1,4). b: (D,). Out: (B,L,D).
//
// HBM-bound, demand-limited. Fix: register-funded MLP. launch_bounds(256,2)
// lifts the reg cap to 128; each 8-row tile batch-issues 8 independent
// LDG.128s into a register window array before computing/storing, giving
// MLP=8 per thread (~64KB outstanding/SM). Work split identical to the
// best-measured R2 schedule (1024 blocks, 32 rows each).

#define CC_B 8
#define CC_L 4096
#define CC_D 1024
#define CC_K 4
#define CC_DV (CC_D / 4)             // 256 float4 lanes over D
#define CC_LC 32                     // rows per block
#define CC_TILE 8                    // rows per load batch
#define CC_NCHUNK (CC_L / CC_LC)     // 128
#define CC_GRID (CC_B * CC_NCHUNK)   // 1024

__global__ __launch_bounds__(CC_DV, 2)
void causal_conv1d_kernel(const float4* __restrict__ x,
                          const float*  __restrict__ w,
                          const float4* __restrict__ bias,
                          float4*       __restrict__ y)
{
    const int d4    = threadIdx.x;           // 0..255
    const int d0    = d4 * 4;
    const int chunk = blockIdx.x & (CC_NCHUNK - 1);
    const int b     = blockIdx.x >> 7;
    const int l0    = chunk * CC_LC;

    // Weights regrouped by tap: wk[k].{x,y,z,w} = tap k of channels d0..d0+3.
    float4 wk0, wk1, wk2, wk3;
    wk0.x = w[(d0 + 0) * CC_K + 0]; wk0.y = w[(d0 + 1) * CC_K + 0];
    wk0.z = w[(d0 + 2) * CC_K + 0]; wk0.w = w[(d0 + 3) * CC_K + 0];
    wk1.x = w[(d0 + 0) * CC_K + 1]; wk1.y = w[(d0 + 1) * CC_K + 1];
    wk1.z = w[(d0 + 2) * CC_K + 1]; wk1.w = w[(d0 + 3) * CC_K + 1];
    wk2.x = w[(d0 + 0) * CC_K + 2]; wk2.y = w[(d0 + 1) * CC_K + 2];
    wk2.z = w[(d0 + 2) * CC_K + 2]; wk2.w = w[(d0 + 3) * CC_K + 2];
    wk3.x = w[(d0 + 0) * CC_K + 3]; wk3.y = w[(d0 + 1) * CC_K + 3];
    wk3.z = w[(d0 + 2) * CC_K + 3]; wk3.w = w[(d0 + 3) * CC_K + 3];

    const float4 bv = bias[d4];

    const size_t rowbase = (size_t)b * CC_L * CC_DV + d4;

    // v[0..2] = sliding window (x[l-3..l-1]); v[3..10] = current 8-row tile.
    float4 v[CC_TILE + 3];
    if (l0 == 0) {
        v[0] = make_float4(0.f, 0.f, 0.f, 0.f);
        v[1] = v[0];
        v[2] = v[0];
    } else {
        v[0] = x[rowbase + (size_t)(l0 - 3) * CC_DV];
        v[1] = x[rowbase + (size_t)(l0 - 2) * CC_DV];
        v[2] = x[rowbase + (size_t)(l0 - 1) * CC_DV];
    }

    #pragma unroll
    for (int t = 0; t < CC_LC / CC_TILE; t++) {
        const size_t tb = rowbase + (size_t)(l0 + t * CC_TILE) * CC_DV;

        // Batch-issue 8 independent LDG.128s (MLP=8) before any consumer.
        #pragma unroll
        for (int i = 0; i < CC_TILE; i++)
            v[3 + i] = x[tb + (size_t)i * CC_DV];

        // Compute + store 8 rows.
        #pragma unroll
        for (int i = 0; i < CC_TILE; i++) {
            const float4 a3 = v[i], a2 = v[i + 1], a1 = v[i + 2], a0 = v[i + 3];
            float4 r;
            r.x = fmaf(wk0.x, a3.x, fmaf(wk1.x, a2.x, fmaf(wk2.x, a1.x, fmaf(wk3.x, a0.x, bv.x))));
            r.y = fmaf(wk0.y, a3.y, fmaf(wk1.y, a2.y, fmaf(wk2.y, a1.y, fmaf(wk3.y, a0.y, bv.y))));
            r.z = fmaf(wk0.z, a3.z, fmaf(wk1.z, a2.z, fmaf(wk2.z, a1.z, fmaf(wk3.z, a0.z, bv.z))));
            r.w = fmaf(wk0.w, a3.w, fmaf(wk1.w, a2.w, fmaf(wk2.w, a1.w, fmaf(wk3.w, a0.w, bv.w))));
            y[tb + (size_t)i * CC_DV] = r;
        }

        // Roll window: last 3 rows of this tile feed the next tile.
        v[0] = v[CC_TILE];
        v[1] = v[CC_TILE + 1];
        v[2] = v[CC_TILE + 2];
    }
}

extern "C" void kernel_launch(void* const* d_in, const int* in_sizes, int n_in,
                              void* d_out, int out_size)
{
    (void)in_sizes; (void)n_in; (void)out_size;
    const float4* x    = (const float4*)d_in[0];
    const float*  w    = (const float*)d_in[1];
    const float4* bias = (const float4*)d_in[2];
    float4*       y    = (float4*)d_out;

    causal_conv1d_kernel<<<CC_GRID, CC_DV>>>(x, w, bias, y);
}